// round 7
// baseline (speedup 1.0000x reference)
#include <cuda_runtime.h>
#include <cuda_bf16.h>
#include <cstdint>

// out[b,r] = sum_k Xa[b,k]*G[k,r] + C[r]   (Gaussian NB log-likelihood as GEMM)
//   Xa[b,k] = x[b,k] (k<512), x[b,k-512]^2 (k>=512), x = concat(sbjs, objs)
//   G[k,r]  = mu[r,k]/sig^2 (k<512), -0.5/sig^2 (k>=512)
//   C[r]    = sum_d(-0.5*mu^2/sig^2 - log sig) - 512*LOG_SQRT_2PI + 512*prior[r]
// Single persistent kernel, grid 1024 co-resident CTAs, device-wide spin
// barriers between phases:
//   P1: convert B to bf16 + C partial sums      (1024 = 128 r x 8 d-groups)
//   P2: mma.sync bf16 GEMM, K-split x4, fp32 partials to scratch
//   P3: fixed-order reduce: 4 partials + C(8 parts) + prior -> out

#define BATCH 4096
#define EMB   256
#define TWO_D 512
#define NREL  128
#define KDIM  1024
#define KSPLIT 4
#define GRID_SZ 1024

#define ROWB   144              // smem row pitch bytes (64 halves + 8 pad)
#define A_TILE (32 * ROWB)      // 4608 B
#define B_TILE (64 * ROWB)      // 9216 B

__device__ __nv_bfloat16 g_B[NREL * KDIM];            // 256 KB
__device__ float g_Cpart[8 * NREL];                   // 8 d-group partials
__device__ float g_partial[KSPLIT * BATCH * NREL];    // 8 MB scratch
__device__ unsigned g_cnt = 0;
__device__ volatile unsigned g_gen = 0;

__device__ __forceinline__ uint32_t smem_u32(const void* p) {
    uint32_t a;
    asm("{ .reg .u64 t; cvta.to.shared.u64 t, %1; cvt.u32.u64 %0, t; }"
        : "=r"(a) : "l"(p));
    return a;
}

#define LDSM4(r, addr) \
    asm volatile("ldmatrix.sync.aligned.m8n8.x4.shared.b16 {%0,%1,%2,%3}, [%4];" \
        : "=r"((r)[0]), "=r"((r)[1]), "=r"((r)[2]), "=r"((r)[3]) : "r"(addr))

__device__ __forceinline__ void mma16816(float* c, const uint32_t* a,
                                         uint32_t b0, uint32_t b1) {
    asm("mma.sync.aligned.m16n8k16.row.col.f32.bf16.bf16.f32 "
        "{%0,%1,%2,%3}, {%4,%5,%6,%7}, {%8,%9}, {%0,%1,%2,%3};"
        : "+f"(c[0]), "+f"(c[1]), "+f"(c[2]), "+f"(c[3])
        : "r"(a[0]), "r"(a[1]), "r"(a[2]), "r"(a[3]), "r"(b0), "r"(b1));
}

#define CP_ASYNC16(dst, src) \
    asm volatile("cp.async.cg.shared.global [%0], [%1], 16;" \
        :: "r"(dst), "l"(src) : "memory")
#define CP_COMMIT() asm volatile("cp.async.commit_group;" ::: "memory")
#define CP_WAIT0()  asm volatile("cp.async.wait_group 0;" ::: "memory")

// Device-wide barrier. Safe: grid 1024 <= co-resident capacity 1036
// (launch_bounds(128,7): regs<=73; smem 27.6KB -> 7 CTAs/SM on 148 SMs).
// Generation counter is monotone across graph replays.
__device__ __forceinline__ void grid_barrier() {
    __syncthreads();
    if (threadIdx.x == 0) {
        unsigned gen = g_gen;
        __threadfence();
        if (atomicAdd(&g_cnt, 1) == GRID_SZ - 1) {
            g_cnt = 0;
            __threadfence();
            g_gen = gen + 1;
        } else {
            while (g_gen == gen) __nanosleep(64);
        }
        __threadfence();
    }
    __syncthreads();
}

__global__ void __launch_bounds__(128, 7) nb_fused(
    const float* __restrict__ sbjs,
    const float* __restrict__ objs,
    const float* __restrict__ mus,
    const float* __restrict__ sigmas,
    const float* __restrict__ priors,
    float* __restrict__ out)
{
    __shared__ __align__(16) char smA[2 * A_TILE];
    __shared__ __align__(16) char smB[2 * B_TILE];
    __shared__ float s_red[2];

    const int tid  = threadIdx.x;
    const int lane = tid & 31;
    const int wid  = tid >> 5;
    const int bid  = blockIdx.x;

    // ================= Phase 1: B conversion + C partials =================
    {
        const int r    = bid >> 3;            // 0..127
        const int dgrp = bid & 7;             // 0..7
        if (tid < 64) {
            const int d = dgrp * 64 + tid;
            float mu = mus[r * TWO_D + d];
            float s  = sigmas[r * TWO_D + d];
            float inv = 1.0f / (s * s);
            g_B[r * KDIM + d]         = __float2bfloat16_rn(mu * inv);
            g_B[r * KDIM + TWO_D + d] = __float2bfloat16_rn(-0.5f * inv);
            float c = fmaf(-0.5f * mu, mu * inv, -__logf(s));
            #pragma unroll
            for (int o = 16; o > 0; o >>= 1)
                c += __shfl_xor_sync(0xffffffffu, c, o);
            if (lane == 0) s_red[wid] = c;
        }
        __syncthreads();
        if (tid == 0)
            g_Cpart[dgrp * NREL + r] = s_red[0] + s_red[1];
    }

    // ================= Phase 2: GEMM (round-5 config) =====================
    const int mt = bid & 127;
    const int nt = (bid >> 7) & 1;
    const int ks = bid >> 8;
    const int b0 = mt * 32;
    const int n0 = nt * 64;

    const uint32_t sA = smem_u32(smA);
    const uint32_t sB = smem_u32(smB);

    float acc[4][4];
    #pragma unroll
    for (int f = 0; f < 4; f++)
        #pragma unroll
        for (int i = 0; i < 4; i++) acc[f][i] = 0.0f;

    const int xrow  = tid >> 2;
    const int xc    = tid & 3;
    const int brow  = tid >> 1;
    const int bseg0 = (tid & 1) * 4;

    float4 xv[4];

    auto ldgX = [&](int gc) {
        const float4* src = (const float4*)(((gc >> 2) & 1) ? objs : sbjs);
        const float4* p = src + (size_t)(b0 + xrow) * (EMB / 4)
                              + (gc & 3) * 16 + xc;
        #pragma unroll
        for (int j = 0; j < 4; j++) xv[j] = p[4 * j];
    };
    auto cpB = [&](int gc, int stage) {
        const __nv_bfloat16* gp = g_B + (size_t)(n0 + brow) * KDIM
                                      + gc * 64 + bseg0 * 8;
        uint32_t dst = sB + stage * B_TILE + brow * ROWB + bseg0 * 16;
        #pragma unroll
        for (int j = 0; j < 4; j++)
            CP_ASYNC16(dst + j * 16, gp + j * 8);
        CP_COMMIT();
    };

    ldgX(ks * 4);          // X prologue hoisted above the barrier (no g_B dep)

    grid_barrier();        // g_B fully written

    cpB(ks * 4, 0);

    const uint32_t aBase = sA + ((lane & 15)) * ROWB + (lane >> 4) * 16
                              + (wid & 1) * 16 * ROWB;
    const uint32_t bBase = sB + ((wid >> 1) * 32 + (lane & 7)
                              + ((lane >> 4) << 3)) * ROWB
                              + ((lane >> 3) & 1) * 16;

    for (int c = 0; c < 4; c++) {
        const int gc    = ks * 4 + c;
        const int stage = c & 1;
        const bool sq   = (gc >= 8);

        #pragma unroll
        for (int j = 0; j < 4; j++) {
            float4 v = xv[j];
            if (sq) { v.x *= v.x; v.y *= v.y; v.z *= v.z; v.w *= v.w; }
            __nv_bfloat16 h0 = __float2bfloat16_rn(v.x);
            __nv_bfloat16 h1 = __float2bfloat16_rn(v.y);
            __nv_bfloat16 h2 = __float2bfloat16_rn(v.z);
            __nv_bfloat16 h3 = __float2bfloat16_rn(v.w);
            uint2 hi;
            hi.x = (uint32_t)__bfloat16_as_ushort(h0)
                 | ((uint32_t)__bfloat16_as_ushort(h1) << 16);
            hi.y = (uint32_t)__bfloat16_as_ushort(h2)
                 | ((uint32_t)__bfloat16_as_ushort(h3) << 16);
            int off = xrow * ROWB + (xc + 4 * j) * 8;
            *(uint2*)(smA + stage * A_TILE + off) = hi;
        }

        CP_WAIT0();
        __syncthreads();

        if (c < 3) {
            ldgX(gc + 1);
            cpB(gc + 1, stage ^ 1);
        }

        const uint32_t aH = aBase + stage * A_TILE;
        const uint32_t bA = bBase + stage * B_TILE;

        #pragma unroll
        for (int kk = 0; kk < 4; kk++) {
            uint32_t ah[4], br0[4], br1[4];
            LDSM4(ah, aH + kk * 32);
            LDSM4(br0, bA + kk * 32);
            LDSM4(br1, bA + 16 * ROWB + kk * 32);
            mma16816(acc[0], ah, br0[0], br0[1]);
            mma16816(acc[1], ah, br0[2], br0[3]);
            mma16816(acc[2], ah, br1[0], br1[1]);
            mma16816(acc[3], ah, br1[2], br1[3]);
        }
    }

    // epilogue: fp32 partials to scratch
    {
        float* pout = g_partial + (size_t)ks * (BATCH * NREL);
        const int wm = wid & 1, wn = wid >> 1;
        const int r0 = b0 + wm * 16 + (lane >> 2);
        #pragma unroll
        for (int f = 0; f < 4; f++) {
            int col = n0 + wn * 32 + f * 8 + (lane & 3) * 2;
            *(float2*)&pout[(size_t)r0 * NREL + col] =
                make_float2(acc[f][0], acc[f][1]);
            *(float2*)&pout[(size_t)(r0 + 8) * NREL + col] =
                make_float2(acc[f][2], acc[f][3]);
        }
    }

    grid_barrier();        // all partials written

    // ================= Phase 3: reduce (1 float4 per thread) ==============
    {
        const int idx = bid * 128 + tid;            // 0..131071 float4
        const int P   = BATCH * NREL / 4;
        const int rg  = idx & (NREL / 4 - 1);
        const float4* p = (const float4*)g_partial;
        float4 a = __ldcg(&p[idx]);
        float4 b = __ldcg(&p[idx + P]);
        float4 c = __ldcg(&p[idx + 2 * P]);
        float4 d = __ldcg(&p[idx + 3 * P]);
        float4 cp[8];
        #pragma unroll
        for (int j = 0; j < 8; j++)
            cp[j] = __ldcg(&((const float4*)(g_Cpart + j * NREL))[rg]);
        float4 pr = ((const float4*)priors)[rg];
        const float K0 = -(float)TWO_D * 0.9189385332046727f;
        float4 C;
        C.x = ((cp[0].x + cp[1].x) + (cp[2].x + cp[3].x))
            + ((cp[4].x + cp[5].x) + (cp[6].x + cp[7].x))
            + fmaf(pr.x, (float)TWO_D, K0);
        C.y = ((cp[0].y + cp[1].y) + (cp[2].y + cp[3].y))
            + ((cp[4].y + cp[5].y) + (cp[6].y + cp[7].y))
            + fmaf(pr.y, (float)TWO_D, K0);
        C.z = ((cp[0].z + cp[1].z) + (cp[2].z + cp[3].z))
            + ((cp[4].z + cp[5].z) + (cp[6].z + cp[7].z))
            + fmaf(pr.z, (float)TWO_D, K0);
        C.w = ((cp[0].w + cp[1].w) + (cp[2].w + cp[3].w))
            + ((cp[4].w + cp[5].w) + (cp[6].w + cp[7].w))
            + fmaf(pr.w, (float)TWO_D, K0);
        float4 o;
        o.x = (a.x + b.x) + (c.x + d.x) + C.x;
        o.y = (a.y + b.y) + (c.y + d.y) + C.y;
        o.z = (a.z + b.z) + (c.z + d.z) + C.z;
        o.w = (a.w + b.w) + (c.w + d.w) + C.w;
        ((float4*)out)[idx] = o;
    }
}

extern "C" void kernel_launch(void* const* d_in, const int* in_sizes, int n_in,
                              void* d_out, int out_size)
{
    const float* sbjs   = (const float*)d_in[0];
    const float* objs   = (const float*)d_in[1];
    const float* mus    = (const float*)d_in[2];
    const float* sigmas = (const float*)d_in[3];
    const float* priors = (const float*)d_in[4];
    float* out = (float*)d_out;

    nb_fused<<<GRID_SZ, 128>>>(sbjs, objs, mus, sigmas, priors, out);
}

// round 8
// speedup vs baseline: 1.2472x; 1.2472x over previous
#include <cuda_runtime.h>
#include <cuda_bf16.h>
#include <cstdint>

// out[b,r] = sum_k Xa[b,k]*G[k,r] + C[r]   (Gaussian NB log-likelihood as GEMM)
//   Xa[b,k] = x[b,k] (k<512), x[b,k-512]^2 (k>=512), x = concat(sbjs, objs)
//   G[k,r]  = mu[r,k]/sig^2 (k<512), -0.5/sig^2 (k>=512)
//   C[r]    = sum_d(-0.5*mu^2/sig^2 - log sig) - 512*LOG_SQRT_2PI + 512*prior[r]
// Three kernels:
//   nb_convert: materialize bf16 Xa (8MB) and bf16 B + C (1152 CTAs)
//   nb_mma:     pure cp.async+ldmatrix+mma GEMM, K-split x4, fp32 partials
//   nb_reduce:  fixed-order sum of 4 partials + C -> out (deterministic)

#define BATCH 4096
#define EMB   256
#define TWO_D 512
#define NREL  128
#define KDIM  1024
#define KSPLIT 4

#define ROWB   144              // smem row pitch bytes (64 halves + 8 pad)
#define A_TILE (32 * ROWB)      // 4608 B
#define B_TILE (64 * ROWB)      // 9216 B

__device__ __nv_bfloat16 g_A[BATCH * KDIM];           // 8 MB bf16 Xa
__device__ __nv_bfloat16 g_B[NREL * KDIM];            // 256 KB
__device__ float g_C[NREL];
__device__ float g_partial[KSPLIT * BATCH * NREL];    // 8 MB scratch

__device__ __forceinline__ uint32_t smem_u32(const void* p) {
    uint32_t a;
    asm("{ .reg .u64 t; cvta.to.shared.u64 t, %1; cvt.u32.u64 %0, t; }"
        : "=r"(a) : "l"(p));
    return a;
}

#define LDSM4(r, addr) \
    asm volatile("ldmatrix.sync.aligned.m8n8.x4.shared.b16 {%0,%1,%2,%3}, [%4];" \
        : "=r"((r)[0]), "=r"((r)[1]), "=r"((r)[2]), "=r"((r)[3]) : "r"(addr))

__device__ __forceinline__ void mma16816(float* c, const uint32_t* a,
                                         uint32_t b0, uint32_t b1) {
    asm("mma.sync.aligned.m16n8k16.row.col.f32.bf16.bf16.f32 "
        "{%0,%1,%2,%3}, {%4,%5,%6,%7}, {%8,%9}, {%0,%1,%2,%3};"
        : "+f"(c[0]), "+f"(c[1]), "+f"(c[2]), "+f"(c[3])
        : "r"(a[0]), "r"(a[1]), "r"(a[2]), "r"(a[3]), "r"(b0), "r"(b1));
}

#define CP_ASYNC16(dst, src) \
    asm volatile("cp.async.cg.shared.global [%0], [%1], 16;" \
        :: "r"(dst), "l"(src) : "memory")
#define CP_COMMIT() asm volatile("cp.async.commit_group;" ::: "memory")
#define CP_WAIT0()  asm volatile("cp.async.wait_group 0;" ::: "memory")

// ---------------------------------------------------------------------------
// Convert: bid < 1024 -> Xa bf16 (4 batch rows per CTA);
//          bid >= 1024 -> B bf16 + C for relation bid-1024.
// ---------------------------------------------------------------------------
__global__ void __launch_bounds__(256) nb_convert(
    const float* __restrict__ sbjs,
    const float* __restrict__ objs,
    const float* __restrict__ mus,
    const float* __restrict__ sigmas,
    const float* __restrict__ priors)
{
    const int tid = threadIdx.x;
    const int bid = blockIdx.x;

    if (bid < 1024) {
        // Xa: global float4 ids [bid*512, bid*512+512)
        #pragma unroll
        for (int j = 0; j < 2; j++) {
            int g   = bid * 512 + tid + 256 * j;
            int row = g >> 7;            // batch row
            int c   = g & 127;           // float4 col within 512 floats
            float4 v = (c < 64)
                ? ((const float4*)sbjs)[row * 64 + c]
                : ((const float4*)objs)[row * 64 + (c - 64)];
            __nv_bfloat16* dst = g_A + (size_t)row * KDIM + c * 4;
            uint2 lin, sq;
            __nv_bfloat16 h0 = __float2bfloat16_rn(v.x);
            __nv_bfloat16 h1 = __float2bfloat16_rn(v.y);
            __nv_bfloat16 h2 = __float2bfloat16_rn(v.z);
            __nv_bfloat16 h3 = __float2bfloat16_rn(v.w);
            lin.x = (uint32_t)__bfloat16_as_ushort(h0)
                  | ((uint32_t)__bfloat16_as_ushort(h1) << 16);
            lin.y = (uint32_t)__bfloat16_as_ushort(h2)
                  | ((uint32_t)__bfloat16_as_ushort(h3) << 16);
            __nv_bfloat16 q0 = __float2bfloat16_rn(v.x * v.x);
            __nv_bfloat16 q1 = __float2bfloat16_rn(v.y * v.y);
            __nv_bfloat16 q2 = __float2bfloat16_rn(v.z * v.z);
            __nv_bfloat16 q3 = __float2bfloat16_rn(v.w * v.w);
            sq.x = (uint32_t)__bfloat16_as_ushort(q0)
                 | ((uint32_t)__bfloat16_as_ushort(q1) << 16);
            sq.y = (uint32_t)__bfloat16_as_ushort(q2)
                 | ((uint32_t)__bfloat16_as_ushort(q3) << 16);
            *(uint2*)dst             = lin;
            *(uint2*)(dst + TWO_D)   = sq;
        }
    } else {
        const int r = bid - 1024;
        __shared__ float red[8];
        float csum = 0.0f;
        #pragma unroll
        for (int j = 0; j < 2; j++) {
            int d = tid + 256 * j;
            float mu = mus[r * TWO_D + d];
            float s  = sigmas[r * TWO_D + d];
            float inv = 1.0f / (s * s);
            g_B[r * KDIM + d]         = __float2bfloat16_rn(mu * inv);
            g_B[r * KDIM + TWO_D + d] = __float2bfloat16_rn(-0.5f * inv);
            csum += fmaf(-0.5f * mu, mu * inv, -__logf(s));
        }
        #pragma unroll
        for (int o = 16; o > 0; o >>= 1)
            csum += __shfl_xor_sync(0xffffffffu, csum, o);
        if ((tid & 31) == 0) red[tid >> 5] = csum;
        __syncthreads();
        if (tid == 0) {
            float v = ((red[0] + red[1]) + (red[2] + red[3]))
                    + ((red[4] + red[5]) + (red[6] + red[7]));
            g_C[r] = v - (float)TWO_D * 0.9189385332046727f
                       + priors[r] * (float)TWO_D;
        }
    }
}

// ---------------------------------------------------------------------------
// GEMM: grid 1024 = ks*256 + nt*128 + mt. CTA: BM=32 x BN=64, K=256 (4
// chunks of 64). 4 warps (2x2), warp tile 16x32. Pure cp.async mainloop.
// ---------------------------------------------------------------------------
__global__ void __launch_bounds__(128, 8) nb_mma(
    const float* __restrict__ dummy)
{
    __shared__ __align__(16) char smA[2 * A_TILE];
    __shared__ __align__(16) char smB[2 * B_TILE];

    const int tid  = threadIdx.x;
    const int lane = tid & 31;
    const int wid  = tid >> 5;
    const int wm   = wid & 1;
    const int wn   = wid >> 1;
    const int bid  = blockIdx.x;
    const int mt   = bid & 127;
    const int nt   = (bid >> 7) & 1;
    const int ks   = bid >> 8;
    const int b0   = mt * 32;
    const int n0   = nt * 64;

    const uint32_t sA = smem_u32(smA);
    const uint32_t sB = smem_u32(smB);

    float acc[4][4];
    #pragma unroll
    for (int f = 0; f < 4; f++)
        #pragma unroll
        for (int i = 0; i < 4; i++) acc[f][i] = 0.0f;

    // A: 256 16B-chunks (32 rows x 8 segs); thread does ids tid, tid+128
    const int ar0 = tid >> 3, as0 = tid & 7;          // id = tid
    const int ar1 = (tid + 128) >> 3, as1 = tid & 7;  // id = tid+128
    // B: 64 rows x 8 segs; thread does brow, 4 segs
    const int brow  = tid >> 1;
    const int bseg0 = (tid & 1) * 4;

    auto cpAB = [&](int gc, int stage) {
        const __nv_bfloat16* ga = g_A + (size_t)b0 * KDIM + gc * 64;
        uint32_t da = sA + stage * A_TILE;
        CP_ASYNC16(da + ar0 * ROWB + as0 * 16, ga + (size_t)ar0 * KDIM + as0 * 8);
        CP_ASYNC16(da + ar1 * ROWB + as1 * 16, ga + (size_t)ar1 * KDIM + as1 * 8);
        const __nv_bfloat16* gb = g_B + (size_t)(n0 + brow) * KDIM
                                      + gc * 64 + bseg0 * 8;
        uint32_t db = sB + stage * B_TILE + brow * ROWB + bseg0 * 16;
        #pragma unroll
        for (int j = 0; j < 4; j++)
            CP_ASYNC16(db + j * 16, gb + j * 8);
        CP_COMMIT();
    };

    cpAB(ks * 4, 0);

    const uint32_t aBase = sA + (wm * 16 + (lane & 15)) * ROWB
                              + (lane >> 4) * 16;
    const uint32_t bBase = sB + (wn * 32 + (lane & 7) + ((lane >> 4) << 3)) * ROWB
                              + ((lane >> 3) & 1) * 16;

    for (int c = 0; c < 4; c++) {
        const int stage = c & 1;

        CP_WAIT0();
        __syncthreads();

        if (c < 3) cpAB(ks * 4 + c + 1, stage ^ 1);

        const uint32_t aH = aBase + stage * A_TILE;
        const uint32_t bA = bBase + stage * B_TILE;

        #pragma unroll
        for (int kk = 0; kk < 4; kk++) {
            uint32_t ah[4], br0[4], br1[4];
            LDSM4(ah, aH + kk * 32);
            LDSM4(br0, bA + kk * 32);
            LDSM4(br1, bA + 16 * ROWB + kk * 32);
            mma16816(acc[0], ah, br0[0], br0[1]);
            mma16816(acc[1], ah, br0[2], br0[3]);
            mma16816(acc[2], ah, br1[0], br1[1]);
            mma16816(acc[3], ah, br1[2], br1[3]);
        }
        __syncthreads();
    }

    // epilogue: fp32 partials
    float* pout = g_partial + (size_t)ks * (BATCH * NREL);
    const int r0 = b0 + wm * 16 + (lane >> 2);
    #pragma unroll
    for (int f = 0; f < 4; f++) {
        int col = n0 + wn * 32 + f * 8 + (lane & 3) * 2;
        *(float2*)&pout[(size_t)r0 * NREL + col] =
            make_float2(acc[f][0], acc[f][1]);
        *(float2*)&pout[(size_t)(r0 + 8) * NREL + col] =
            make_float2(acc[f][2], acc[f][3]);
    }
}

// ---------------------------------------------------------------------------
// out = sum_ks partial[ks] + C  (float4; fixed order = deterministic)
// ---------------------------------------------------------------------------
__global__ void __launch_bounds__(256) nb_reduce(float* __restrict__ out)
{
    const int idx = blockIdx.x * 256 + threadIdx.x;     // float4 index
    const int P   = BATCH * NREL / 4;
    const float4* p = (const float4*)g_partial;
    float4 a = p[idx];
    float4 b = p[idx + P];
    float4 c = p[idx + 2 * P];
    float4 d = p[idx + 3 * P];
    float4 C = ((const float4*)g_C)[idx & (NREL / 4 - 1)];
    float4 o;
    o.x = (a.x + b.x) + (c.x + d.x) + C.x;
    o.y = (a.y + b.y) + (c.y + d.y) + C.y;
    o.z = (a.z + b.z) + (c.z + d.z) + C.z;
    o.w = (a.w + b.w) + (c.w + d.w) + C.w;
    ((float4*)out)[idx] = o;
}

extern "C" void kernel_launch(void* const* d_in, const int* in_sizes, int n_in,
                              void* d_out, int out_size)
{
    const float* sbjs   = (const float*)d_in[0];
    const float* objs   = (const float*)d_in[1];
    const float* mus    = (const float*)d_in[2];
    const float* sigmas = (const float*)d_in[3];
    const float* priors = (const float*)d_in[4];
    float* out = (float*)d_out;

    nb_convert<<<1024 + NREL, 256>>>(sbjs, objs, mus, sigmas, priors);
    nb_mma<<<KSPLIT * (BATCH / 32) * (NREL / 64), 128>>>(nullptr);
    nb_reduce<<<(BATCH * NREL / 4) / 256, 256>>>(out);
}

// round 9
// speedup vs baseline: 1.2490x; 1.0014x over previous
#include <cuda_runtime.h>
#include <cuda_bf16.h>
#include <cstdint>

// out[b,r] = sum_k Xa[b,k]*G[k,r] + C[r]   (Gaussian NB log-likelihood as GEMM)
//   Xa[b,k] = x[b,k] (k<512), x[b,k-512]^2 (k>=512), x = concat(sbjs, objs)
//   G[k,r]  = mu[r,k]/sig^2 (k<512), -0.5/sig^2 (k>=512)
//   C[r]    = sum_d(-0.5*mu^2/sig^2 - log sig) - 512*LOG_SQRT_2PI + 512*prior[r]
// Three kernels:
//   nb_convert: materialize bf16 Xa (8MB, 1 vectorized task/thread) + B + C
//   nb_mma:     pure cp.async+ldmatrix+mma GEMM, K-split x4, fp32 partials
//   nb_reduce:  fixed-order sum of 4 partials + C -> out (deterministic)

#define BATCH 4096
#define EMB   256
#define TWO_D 512
#define NREL  128
#define KDIM  1024
#define KSPLIT 4

#define ROWB   144              // smem row pitch bytes (64 halves + 8 pad)
#define A_TILE (32 * ROWB)      // 4608 B
#define B_TILE (64 * ROWB)      // 9216 B

__device__ __nv_bfloat16 g_A[BATCH * KDIM];           // 8 MB bf16 Xa
__device__ __nv_bfloat16 g_B[NREL * KDIM];            // 256 KB
__device__ float g_C[NREL];
__device__ float g_partial[KSPLIT * BATCH * NREL];    // 8 MB scratch

__device__ __forceinline__ uint32_t smem_u32(const void* p) {
    uint32_t a;
    asm("{ .reg .u64 t; cvta.to.shared.u64 t, %1; cvt.u32.u64 %0, t; }"
        : "=r"(a) : "l"(p));
    return a;
}

#define LDSM4(r, addr) \
    asm volatile("ldmatrix.sync.aligned.m8n8.x4.shared.b16 {%0,%1,%2,%3}, [%4];" \
        : "=r"((r)[0]), "=r"((r)[1]), "=r"((r)[2]), "=r"((r)[3]) : "r"(addr))

__device__ __forceinline__ void mma16816(float* c, const uint32_t* a,
                                         uint32_t b0, uint32_t b1) {
    asm("mma.sync.aligned.m16n8k16.row.col.f32.bf16.bf16.f32 "
        "{%0,%1,%2,%3}, {%4,%5,%6,%7}, {%8,%9}, {%0,%1,%2,%3};"
        : "+f"(c[0]), "+f"(c[1]), "+f"(c[2]), "+f"(c[3])
        : "r"(a[0]), "r"(a[1]), "r"(a[2]), "r"(a[3]), "r"(b0), "r"(b1));
}

#define CP_ASYNC16(dst, src) \
    asm volatile("cp.async.cg.shared.global [%0], [%1], 16;" \
        :: "r"(dst), "l"(src) : "memory")
#define CP_COMMIT() asm volatile("cp.async.commit_group;" ::: "memory")
#define CP_WAIT0()  asm volatile("cp.async.wait_group 0;" ::: "memory")

__device__ __forceinline__ uint32_t bf2pack(float a, float b) {
    __nv_bfloat162 h = __float22bfloat162_rn(make_float2(a, b));
    return *reinterpret_cast<uint32_t*>(&h);
}

// ---------------------------------------------------------------------------
// Convert. bid < 1024: Xa — exactly one 32B task per thread.
//          bid >= 1024: B bf16 + C for relation bid-1024.
// ---------------------------------------------------------------------------
__global__ void __launch_bounds__(256) nb_convert(
    const float* __restrict__ sbjs,
    const float* __restrict__ objs,
    const float* __restrict__ mus,
    const float* __restrict__ sigmas,
    const float* __restrict__ priors)
{
    const int tid = threadIdx.x;
    const int bid = blockIdx.x;

    if (bid < 1024) {
        // pair-task id: row = p>>6, pc = p&63 (each task = 8 floats = 32B)
        const int p   = bid * 256 + tid;
        const int row = p >> 6;
        const int pc  = p & 63;
        const float4* src;
        int f4;
        if (pc < 32) { src = (const float4*)sbjs; f4 = row * 64 + pc * 2; }
        else         { src = (const float4*)objs; f4 = row * 64 + (pc - 32) * 2; }
        float4 v0 = src[f4];
        float4 v1 = src[f4 + 1];

        uint4 lin, sq;
        lin.x = bf2pack(v0.x, v0.y);
        lin.y = bf2pack(v0.z, v0.w);
        lin.z = bf2pack(v1.x, v1.y);
        lin.w = bf2pack(v1.z, v1.w);
        sq.x  = bf2pack(v0.x * v0.x, v0.y * v0.y);
        sq.y  = bf2pack(v0.z * v0.z, v0.w * v0.w);
        sq.z  = bf2pack(v1.x * v1.x, v1.y * v1.y);
        sq.w  = bf2pack(v1.z * v1.z, v1.w * v1.w);

        __nv_bfloat16* dst = g_A + (size_t)row * KDIM + pc * 8;
        *(uint4*)dst           = lin;
        *(uint4*)(dst + TWO_D) = sq;
    } else {
        const int r = bid - 1024;
        __shared__ float red[8];
        float csum = 0.0f;
        #pragma unroll
        for (int j = 0; j < 2; j++) {
            int d = tid + 256 * j;
            float mu = mus[r * TWO_D + d];
            float s  = sigmas[r * TWO_D + d];
            float inv = 1.0f / (s * s);
            g_B[r * KDIM + d]         = __float2bfloat16_rn(mu * inv);
            g_B[r * KDIM + TWO_D + d] = __float2bfloat16_rn(-0.5f * inv);
            csum += fmaf(-0.5f * mu, mu * inv, -__logf(s));
        }
        #pragma unroll
        for (int o = 16; o > 0; o >>= 1)
            csum += __shfl_xor_sync(0xffffffffu, csum, o);
        if ((tid & 31) == 0) red[tid >> 5] = csum;
        __syncthreads();
        if (tid == 0) {
            float v = ((red[0] + red[1]) + (red[2] + red[3]))
                    + ((red[4] + red[5]) + (red[6] + red[7]));
            g_C[r] = v - (float)TWO_D * 0.9189385332046727f
                       + priors[r] * (float)TWO_D;
        }
    }
}

// ---------------------------------------------------------------------------
// GEMM: grid 1024 = ks*256 + nt*128 + mt. CTA: BM=32 x BN=64, K=256 (4
// chunks of 64, fully unrolled). 4 warps (2x2), warp tile 16x32.
// ---------------------------------------------------------------------------
__global__ void __launch_bounds__(128, 8) nb_mma(
    const float* __restrict__ dummy)
{
    __shared__ __align__(16) char smA[2 * A_TILE];
    __shared__ __align__(16) char smB[2 * B_TILE];

    const int tid  = threadIdx.x;
    const int lane = tid & 31;
    const int wid  = tid >> 5;
    const int wm   = wid & 1;
    const int wn   = wid >> 1;
    const int bid  = blockIdx.x;
    const int mt   = bid & 127;
    const int nt   = (bid >> 7) & 1;
    const int ks   = bid >> 8;
    const int b0   = mt * 32;
    const int n0   = nt * 64;

    const uint32_t sA = smem_u32(smA);
    const uint32_t sB = smem_u32(smB);

    float acc[4][4];
    #pragma unroll
    for (int f = 0; f < 4; f++)
        #pragma unroll
        for (int i = 0; i < 4; i++) acc[f][i] = 0.0f;

    const int ar0 = tid >> 3, as0 = tid & 7;
    const int ar1 = (tid + 128) >> 3;
    const int brow  = tid >> 1;
    const int bseg0 = (tid & 1) * 4;

    auto cpAB = [&](int gc, int stage) {
        const __nv_bfloat16* ga = g_A + (size_t)b0 * KDIM + gc * 64;
        uint32_t da = sA + stage * A_TILE;
        CP_ASYNC16(da + ar0 * ROWB + as0 * 16, ga + (size_t)ar0 * KDIM + as0 * 8);
        CP_ASYNC16(da + ar1 * ROWB + as0 * 16, ga + (size_t)ar1 * KDIM + as0 * 8);
        const __nv_bfloat16* gb = g_B + (size_t)(n0 + brow) * KDIM
                                      + gc * 64 + bseg0 * 8;
        uint32_t db = sB + stage * B_TILE + brow * ROWB + bseg0 * 16;
        #pragma unroll
        for (int j = 0; j < 4; j++)
            CP_ASYNC16(db + j * 16, gb + j * 8);
        CP_COMMIT();
    };

    cpAB(ks * 4, 0);

    const uint32_t aBase = sA + (wm * 16 + (lane & 15)) * ROWB
                              + (lane >> 4) * 16;
    const uint32_t bBase = sB + (wn * 32 + (lane & 7) + ((lane >> 4) << 3)) * ROWB
                              + ((lane >> 3) & 1) * 16;

    #pragma unroll
    for (int c = 0; c < 4; c++) {
        const int stage = c & 1;

        CP_WAIT0();
        __syncthreads();

        if (c < 3) cpAB(ks * 4 + c + 1, stage ^ 1);

        const uint32_t aH = aBase + stage * A_TILE;
        const uint32_t bA = bBase + stage * B_TILE;

        #pragma unroll
        for (int kk = 0; kk < 4; kk++) {
            uint32_t ah[4], br0[4], br1[4];
            LDSM4(ah, aH + kk * 32);
            LDSM4(br0, bA + kk * 32);
            LDSM4(br1, bA + 16 * ROWB + kk * 32);
            mma16816(acc[0], ah, br0[0], br0[1]);
            mma16816(acc[1], ah, br0[2], br0[3]);
            mma16816(acc[2], ah, br1[0], br1[1]);
            mma16816(acc[3], ah, br1[2], br1[3]);
        }
        __syncthreads();
    }

    // epilogue: fp32 partials
    float* pout = g_partial + (size_t)ks * (BATCH * NREL);
    const int r0 = b0 + wm * 16 + (lane >> 2);
    #pragma unroll
    for (int f = 0; f < 4; f++) {
        int col = n0 + wn * 32 + f * 8 + (lane & 3) * 2;
        *(float2*)&pout[(size_t)r0 * NREL + col] =
            make_float2(acc[f][0], acc[f][1]);
        *(float2*)&pout[(size_t)(r0 + 8) * NREL + col] =
            make_float2(acc[f][2], acc[f][3]);
    }
}

// ---------------------------------------------------------------------------
// out = sum_ks partial[ks] + C  (float4; fixed order = deterministic)
// ---------------------------------------------------------------------------
__global__ void __launch_bounds__(256) nb_reduce(float* __restrict__ out)
{
    const int idx = blockIdx.x * 256 + threadIdx.x;     // float4 index
    const int P   = BATCH * NREL / 4;
    const float4* p = (const float4*)g_partial;
    float4 a = p[idx];
    float4 b = p[idx + P];
    float4 c = p[idx + 2 * P];
    float4 d = p[idx + 3 * P];
    float4 C = ((const float4*)g_C)[idx & (NREL / 4 - 1)];
    float4 o;
    o.x = (a.x + b.x) + (c.x + d.x) + C.x;
    o.y = (a.y + b.y) + (c.y + d.y) + C.y;
    o.z = (a.z + b.z) + (c.z + d.z) + C.z;
    o.w = (a.w + b.w) + (c.w + d.w) + C.w;
    ((float4*)out)[idx] = o;
}

extern "C" void kernel_launch(void* const* d_in, const int* in_sizes, int n_in,
                              void* d_out, int out_size)
{
    const float* sbjs   = (const float*)d_in[0];
    const float* objs   = (const float*)d_in[1];
    const float* mus    = (const float*)d_in[2];
    const float* sigmas = (const float*)d_in[3];
    const float* priors = (const float*)d_in[4];
    float* out = (float*)d_out;

    nb_convert<<<1024 + NREL, 256>>>(sbjs, objs, mus, sigmas, priors);
    nb_mma<<<KSPLIT * (BATCH / 32) * (NREL / 64), 128>>>(nullptr);
    nb_reduce<<<(BATCH * NREL / 4) / 256, 256>>>(out);
}

// round 11
// speedup vs baseline: 1.7471x; 1.3988x over previous
#include <cuda_runtime.h>
#include <cuda_bf16.h>
#include <cstdint>

// out[b,r] = sum_k Xa[b,k]*G[k,r] + C[r]   (Gaussian NB log-likelihood as GEMM)
//   Xa[b,k] = x[b,k] (k<512), x[b,k-512]^2 (k>=512), x = concat(sbjs, objs)
//   G[k,r]  = mu[r,k]/sig^2 (k<512), -0.5/sig^2 (k>=512)
//   C[r]    = sum_d(-0.5*mu^2/sig^2 - log sig) - 512*LOG_SQRT_2PI + 512*prior[r]
// nb_convert: bf16 Xa (4 tasks/thread, MLP 8) + bf16 B + C
// nb_mma:     BM64 x BN128 (full N), KSPLIT x4, ALL 4 K-chunks prefetched into
//             distinct smem buffers (cp.async groups, wait_group countdown),
//             warp tile 32x32, fp32 partials.
// nb_reduce:  fixed-order sum of 4 partials + C (deterministic)

#define BATCH 4096
#define EMB   256
#define TWO_D 512
#define NREL  128
#define KDIM  1024
#define KSPLIT 4

#define ROWB    144                 // smem row pitch (64 halves + 8 pad)
#define A_CHUNK (64 * ROWB)         // 9216 B  (64 rows x 64 cols)
#define B_CHUNK (128 * ROWB)        // 18432 B (128 rows x 64 cols)
#define A_ALL   (4 * A_CHUNK)       // 36864
#define SMEM_MMA (4 * A_CHUNK + 4 * B_CHUNK)   // 110592 B

__device__ __nv_bfloat16 g_A[BATCH * KDIM];           // 8 MB bf16 Xa
__device__ __nv_bfloat16 g_B[NREL * KDIM];            // 256 KB
__device__ float g_C[NREL];
__device__ float g_partial[KSPLIT * BATCH * NREL];    // 8 MB scratch

__device__ __forceinline__ uint32_t smem_u32(const void* p) {
    uint32_t a;
    asm("{ .reg .u64 t; cvta.to.shared.u64 t, %1; cvt.u32.u64 %0, t; }"
        : "=r"(a) : "l"(p));
    return a;
}

#define LDSM4(r, addr) \
    asm volatile("ldmatrix.sync.aligned.m8n8.x4.shared.b16 {%0,%1,%2,%3}, [%4];" \
        : "=r"((r)[0]), "=r"((r)[1]), "=r"((r)[2]), "=r"((r)[3]) : "r"(addr))

__device__ __forceinline__ void mma16816(float* c, const uint32_t* a,
                                         uint32_t b0, uint32_t b1) {
    asm("mma.sync.aligned.m16n8k16.row.col.f32.bf16.bf16.f32 "
        "{%0,%1,%2,%3}, {%4,%5,%6,%7}, {%8,%9}, {%0,%1,%2,%3};"
        : "+f"(c[0]), "+f"(c[1]), "+f"(c[2]), "+f"(c[3])
        : "r"(a[0]), "r"(a[1]), "r"(a[2]), "r"(a[3]), "r"(b0), "r"(b1));
}

#define CP_ASYNC16(dst, src) \
    asm volatile("cp.async.cg.shared.global [%0], [%1], 16;" \
        :: "r"(dst), "l"(src) : "memory")
#define CP_COMMIT() asm volatile("cp.async.commit_group;" ::: "memory")

template <int N>
__device__ __forceinline__ void cp_waitg() {
    asm volatile("cp.async.wait_group %0;" :: "n"(N) : "memory");
}

__device__ __forceinline__ uint32_t bf2pack(float a, float b) {
    __nv_bfloat162 h = __float22bfloat162_rn(make_float2(a, b));
    return *reinterpret_cast<uint32_t*>(&h);
}

// ---------------------------------------------------------------------------
// Convert. bid < 256: Xa, 4 interleaved 32B tasks/thread, loads front-batched.
//          bid >= 256: B bf16 + C for relation bid-256.
// ---------------------------------------------------------------------------
__global__ void __launch_bounds__(256) nb_convert(
    const float* __restrict__ sbjs,
    const float* __restrict__ objs,
    const float* __restrict__ mus,
    const float* __restrict__ sigmas,
    const float* __restrict__ priors)
{
    const int tid = threadIdx.x;
    const int bid = blockIdx.x;

    if (bid < 256) {
        float4 v[4][2];
        int rows[4], pcs[4];
        #pragma unroll
        for (int t = 0; t < 4; t++) {
            int tk  = t * 65536 + bid * 256 + tid;   // 262144 pair-tasks
            int row = tk >> 6;
            int pc  = tk & 63;
            rows[t] = row; pcs[t] = pc;
            const float4* src;
            int f4;
            if (pc < 32) { src = (const float4*)sbjs; f4 = row * 64 + pc * 2; }
            else         { src = (const float4*)objs; f4 = row * 64 + (pc - 32) * 2; }
            v[t][0] = src[f4];
            v[t][1] = src[f4 + 1];
        }
        #pragma unroll
        for (int t = 0; t < 4; t++) {
            float4 v0 = v[t][0], v1 = v[t][1];
            uint4 lin, sq;
            lin.x = bf2pack(v0.x, v0.y);
            lin.y = bf2pack(v0.z, v0.w);
            lin.z = bf2pack(v1.x, v1.y);
            lin.w = bf2pack(v1.z, v1.w);
            sq.x  = bf2pack(v0.x * v0.x, v0.y * v0.y);
            sq.y  = bf2pack(v0.z * v0.z, v0.w * v0.w);
            sq.z  = bf2pack(v1.x * v1.x, v1.y * v1.y);
            sq.w  = bf2pack(v1.z * v1.z, v1.w * v1.w);
            __nv_bfloat16* dst = g_A + (size_t)rows[t] * KDIM + pcs[t] * 8;
            *(uint4*)dst           = lin;
            *(uint4*)(dst + TWO_D) = sq;
        }
    } else {
        const int r = bid - 256;
        __shared__ float red[8];
        float csum = 0.0f;
        #pragma unroll
        for (int j = 0; j < 2; j++) {
            int d = tid + 256 * j;
            float mu = mus[r * TWO_D + d];
            float s  = sigmas[r * TWO_D + d];
            float inv = 1.0f / (s * s);
            g_B[r * KDIM + d]         = __float2bfloat16_rn(mu * inv);
            g_B[r * KDIM + TWO_D + d] = __float2bfloat16_rn(-0.5f * inv);
            csum += fmaf(-0.5f * mu, mu * inv, -__logf(s));
        }
        #pragma unroll
        for (int o = 16; o > 0; o >>= 1)
            csum += __shfl_xor_sync(0xffffffffu, csum, o);
        if ((tid & 31) == 0) red[tid >> 5] = csum;
        __syncthreads();
        if (tid == 0) {
            float v = ((red[0] + red[1]) + (red[2] + red[3]))
                    + ((red[4] + red[5]) + (red[6] + red[7]));
            g_C[r] = v - (float)TWO_D * 0.9189385332046727f
                       + priors[r] * (float)TWO_D;
        }
    }
}

// ---------------------------------------------------------------------------
// GEMM: grid 256 = ks*64 + mt. CTA: BM=64 x BN=128 (full N), K=256 as 4
// chunks of 64 in DISTINCT smem buffers (prefetch depth 4, one barrier per
// chunk, no WAR syncs). 8 warps (2x4), warp tile 32x32.
// ---------------------------------------------------------------------------
struct MmaCtx {
    uint32_t aBase, bBase;
    float (*acc)[4][4];
};

template <int C>
__device__ __forceinline__ void mma_chunk(const MmaCtx& cx) {
    cp_waitg<3 - C>();
    __syncthreads();

    const uint32_t aA = cx.aBase + C * A_CHUNK;
    const uint32_t bA = cx.bBase + C * B_CHUNK;

    #pragma unroll
    for (int kk = 0; kk < 4; kk++) {
        uint32_t a0[4], a1[4], br0[4], br1[4];
        LDSM4(a0, aA + kk * 32);
        LDSM4(a1, aA + 16 * ROWB + kk * 32);
        LDSM4(br0, bA + kk * 32);
        LDSM4(br1, bA + 16 * ROWB + kk * 32);
        mma16816(cx.acc[0][0], a0, br0[0], br0[1]);
        mma16816(cx.acc[0][1], a0, br0[2], br0[3]);
        mma16816(cx.acc[0][2], a0, br1[0], br1[1]);
        mma16816(cx.acc[0][3], a0, br1[2], br1[3]);
        mma16816(cx.acc[1][0], a1, br0[0], br0[1]);
        mma16816(cx.acc[1][1], a1, br0[2], br0[3]);
        mma16816(cx.acc[1][2], a1, br1[0], br1[1]);
        mma16816(cx.acc[1][3], a1, br1[2], br1[3]);
    }
}

__global__ void __launch_bounds__(256, 2) nb_mma(
    const float* __restrict__ dummy)
{
    extern __shared__ __align__(16) char sm[];

    const int tid  = threadIdx.x;
    const int lane = tid & 31;
    const int wid  = tid >> 5;
    const int wm   = wid >> 2;         // 0..1 -> m offset wm*32
    const int wn   = wid & 3;          // 0..3 -> n offset wn*32
    const int bid  = blockIdx.x;
    const int mt   = bid & 63;
    const int ks   = bid >> 6;
    const int b0   = mt * 64;

    const uint32_t smb = smem_u32(sm);

    float acc[2][4][4];
    #pragma unroll
    for (int mi = 0; mi < 2; mi++)
        #pragma unroll
        for (int nf = 0; nf < 4; nf++)
            #pragma unroll
            for (int i = 0; i < 4; i++) acc[mi][nf][i] = 0.0f;

    // issue all 4 chunks up-front: 2 A ops + 4 B ops per thread per chunk
    {
        const int row2 = tid >> 3, seg = tid & 7;
        #pragma unroll
        for (int c = 0; c < 4; c++) {
            const __nv_bfloat16* ga = g_A + (size_t)b0 * KDIM
                                          + ks * 256 + c * 64;
            uint32_t da = smb + c * A_CHUNK;
            CP_ASYNC16(da + row2 * ROWB + seg * 16,
                       ga + (size_t)row2 * KDIM + seg * 8);
            CP_ASYNC16(da + (row2 + 32) * ROWB + seg * 16,
                       ga + (size_t)(row2 + 32) * KDIM + seg * 8);
            const __nv_bfloat16* gb = g_B + ks * 256 + c * 64;
            uint32_t db = smb + A_ALL + c * B_CHUNK;
            #pragma unroll
            for (int j = 0; j < 4; j++) {
                int i = tid + 256 * j;
                int br = i >> 3, bs = i & 7;
                CP_ASYNC16(db + br * ROWB + bs * 16,
                           gb + (size_t)br * KDIM + bs * 8);
            }
            CP_COMMIT();
        }
    }

    MmaCtx cx;
    cx.aBase = smb + (wm * 32 + (lane & 15)) * ROWB + (lane >> 4) * 16;
    cx.bBase = smb + A_ALL
             + (wn * 32 + (lane & 7) + ((lane >> 4) << 3)) * ROWB
             + ((lane >> 3) & 1) * 16;
    cx.acc = acc;

    mma_chunk<0>(cx);
    mma_chunk<1>(cx);
    mma_chunk<2>(cx);
    mma_chunk<3>(cx);

    // epilogue: fp32 partials
    float* pout = g_partial + (size_t)ks * (BATCH * NREL);
    #pragma unroll
    for (int mi = 0; mi < 2; mi++) {
        const int r0 = b0 + wm * 32 + mi * 16 + (lane >> 2);
        #pragma unroll
        for (int nf = 0; nf < 4; nf++) {
            const float* a = acc[mi][nf];
            int col = wn * 32 + nf * 8 + (lane & 3) * 2;
            *(float2*)&pout[(size_t)r0 * NREL + col] =
                make_float2(a[0], a[1]);
            *(float2*)&pout[(size_t)(r0 + 8) * NREL + col] =
                make_float2(a[2], a[3]);
        }
    }
}

// ---------------------------------------------------------------------------
// out = sum_ks partial[ks] + C  (float4; fixed order = deterministic)
// ---------------------------------------------------------------------------
__global__ void __launch_bounds__(256) nb_reduce(float* __restrict__ out)
{
    const int idx = blockIdx.x * 256 + threadIdx.x;     // float4 index
    const int P   = BATCH * NREL / 4;
    const float4* p = (const float4*)g_partial;
    float4 a = p[idx];
    float4 b = p[idx + P];
    float4 c = p[idx + 2 * P];
    float4 d = p[idx + 3 * P];
    float4 C = ((const float4*)g_C)[idx & (NREL / 4 - 1)];
    float4 o;
    o.x = (a.x + b.x) + (c.x + d.x) + C.x;
    o.y = (a.y + b.y) + (c.y + d.y) + C.y;
    o.z = (a.z + b.z) + (c.z + d.z) + C.z;
    o.w = (a.w + b.w) + (c.w + d.w) + C.w;
    ((float4*)out)[idx] = o;
}

extern "C" void kernel_launch(void* const* d_in, const int* in_sizes, int n_in,
                              void* d_out, int out_size)
{
    const float* sbjs   = (const float*)d_in[0];
    const float* objs   = (const float*)d_in[1];
    const float* mus    = (const float*)d_in[2];
    const float* sigmas = (const float*)d_in[3];
    const float* priors = (const float*)d_in[4];
    float* out = (float*)d_out;

    cudaFuncSetAttribute(nb_mma,
                         cudaFuncAttributeMaxDynamicSharedMemorySize, SMEM_MMA);

    nb_convert<<<256 + NREL, 256>>>(sbjs, objs, mus, sigmas, priors);
    nb_mma<<<KSPLIT * (BATCH / 64), 256, SMEM_MMA>>>(nullptr);
    nb_reduce<<<(BATCH * NREL / 4) / 256, 256>>>(out);
}

// round 12
// speedup vs baseline: 1.9066x; 1.0913x over previous
#include <cuda_runtime.h>
#include <cuda_bf16.h>
#include <cstdint>

// out[b,r] = sum_k Xa[b,k]*G[k,r] + C[r]   (Gaussian NB log-likelihood as GEMM)
//   Xa[b,k] = x[b,k] (k<512), x[b,k-512]^2 (k>=512), x = concat(sbjs, objs)
//   G[k,r]  = mu[r,k]/sig^2 (k<512), -0.5/sig^2 (k>=512)
//   C[r]    = sum_d(-0.5*mu^2/sig^2 - log sig) - 512*LOG_SQRT_2PI + 512*prior[r]
// nb_prep:   bf16 B + C (128 CTAs)
// nb_mma:    BM64 x BN128 (full N). K-split x4 over X-COLUMNS: each ks does
//            both lin and sq K-regions of its 128 x-cols (256 k). X loaded
//            fp32 ONCE (front-batched LDG), converted in-register, STS to 4
//            chunk buffers; B prefetched via cp.async (2 pair groups).
// nb_reduce: fixed-order sum of 4 partials + C (deterministic)

#define BATCH 4096
#define EMB   256
#define TWO_D 512
#define NREL  128
#define KDIM  1024
#define KSPLIT 4

#define ROWB    144                 // smem row pitch (64 halves + 8 pad)
#define A_CHUNK (64 * ROWB)         // 9216 B  (64 rows x 64 halves)
#define B_CHUNK (128 * ROWB)        // 18432 B (128 rows x 64 halves)
#define A_ALL   (4 * A_CHUNK)       // 36864
#define SMEM_MMA (4 * A_CHUNK + 4 * B_CHUNK)   // 110592 B

__device__ __nv_bfloat16 g_B[NREL * KDIM];            // 256 KB (L2-resident)
__device__ float g_C[NREL];
__device__ float g_partial[KSPLIT * BATCH * NREL];    // 8 MB scratch

__device__ __forceinline__ uint32_t smem_u32(const void* p) {
    uint32_t a;
    asm("{ .reg .u64 t; cvta.to.shared.u64 t, %1; cvt.u32.u64 %0, t; }"
        : "=r"(a) : "l"(p));
    return a;
}

#define LDSM4(r, addr) \
    asm volatile("ldmatrix.sync.aligned.m8n8.x4.shared.b16 {%0,%1,%2,%3}, [%4];" \
        : "=r"((r)[0]), "=r"((r)[1]), "=r"((r)[2]), "=r"((r)[3]) : "r"(addr))

__device__ __forceinline__ void mma16816(float* c, const uint32_t* a,
                                         uint32_t b0, uint32_t b1) {
    asm("mma.sync.aligned.m16n8k16.row.col.f32.bf16.bf16.f32 "
        "{%0,%1,%2,%3}, {%4,%5,%6,%7}, {%8,%9}, {%0,%1,%2,%3};"
        : "+f"(c[0]), "+f"(c[1]), "+f"(c[2]), "+f"(c[3])
        : "r"(a[0]), "r"(a[1]), "r"(a[2]), "r"(a[3]), "r"(b0), "r"(b1));
}

#define CP_ASYNC16(dst, src) \
    asm volatile("cp.async.cg.shared.global [%0], [%1], 16;" \
        :: "r"(dst), "l"(src) : "memory")
#define CP_COMMIT() asm volatile("cp.async.commit_group;" ::: "memory")

template <int N>
__device__ __forceinline__ void cp_waitg() {
    asm volatile("cp.async.wait_group %0;" :: "n"(N) : "memory");
}

__device__ __forceinline__ uint32_t bf2pack(float a, float b) {
    __nv_bfloat162 h = __float22bfloat162_rn(make_float2(a, b));
    return *reinterpret_cast<uint32_t*>(&h);
}

// ---------------------------------------------------------------------------
// Prep: bf16 B + C. One CTA per relation.
// ---------------------------------------------------------------------------
__global__ void __launch_bounds__(256) nb_prep(
    const float* __restrict__ mus,
    const float* __restrict__ sigmas,
    const float* __restrict__ priors)
{
    const int r   = blockIdx.x;
    const int tid = threadIdx.x;
    __shared__ float red[8];

    float csum = 0.0f;
    #pragma unroll
    for (int j = 0; j < 2; j++) {
        int d = tid + 256 * j;
        float mu = mus[r * TWO_D + d];
        float s  = sigmas[r * TWO_D + d];
        float inv = 1.0f / (s * s);
        g_B[r * KDIM + d]         = __float2bfloat16_rn(mu * inv);
        g_B[r * KDIM + TWO_D + d] = __float2bfloat16_rn(-0.5f * inv);
        csum += fmaf(-0.5f * mu, mu * inv, -__logf(s));
    }
    #pragma unroll
    for (int o = 16; o > 0; o >>= 1)
        csum += __shfl_xor_sync(0xffffffffu, csum, o);
    if ((tid & 31) == 0) red[tid >> 5] = csum;
    __syncthreads();
    if (tid == 0) {
        float v = ((red[0] + red[1]) + (red[2] + red[3]))
                + ((red[4] + red[5]) + (red[6] + red[7]));
        g_C[r] = v - (float)TWO_D * 0.9189385332046727f
                   + priors[r] * (float)TWO_D;
    }
}

// ---------------------------------------------------------------------------
// GEMM. grid 256 = ks*64 + mt. CTA: BM=64 x BN=128, 4 K-chunks of 64:
// [lin p0, sq p0, lin p1, sq p1] where pair p covers x-cols
// ks*128 + p*64 .. +64. 8 warps (2x4), warp tile 32x32.
// ---------------------------------------------------------------------------
struct MmaCtx {
    uint32_t aBase, bBase;
    float (*acc)[4][4];
};

template <int C>
__device__ __forceinline__ void mma_chunk(const MmaCtx& cx) {
    const uint32_t aA = cx.aBase + C * A_CHUNK;
    const uint32_t bA = cx.bBase + C * B_CHUNK;
    #pragma unroll
    for (int kk = 0; kk < 4; kk++) {
        uint32_t a0[4], a1[4], br0[4], br1[4];
        LDSM4(a0, aA + kk * 32);
        LDSM4(a1, aA + 16 * ROWB + kk * 32);
        LDSM4(br0, bA + kk * 32);
        LDSM4(br1, bA + 16 * ROWB + kk * 32);
        mma16816(cx.acc[0][0], a0, br0[0], br0[1]);
        mma16816(cx.acc[0][1], a0, br0[2], br0[3]);
        mma16816(cx.acc[0][2], a0, br1[0], br1[1]);
        mma16816(cx.acc[0][3], a0, br1[2], br1[3]);
        mma16816(cx.acc[1][0], a1, br0[0], br0[1]);
        mma16816(cx.acc[1][1], a1, br0[2], br0[3]);
        mma16816(cx.acc[1][2], a1, br1[0], br1[1]);
        mma16816(cx.acc[1][3], a1, br1[2], br1[3]);
    }
}

__global__ void __launch_bounds__(256, 2) nb_mma(
    const float* __restrict__ sbjs,
    const float* __restrict__ objs)
{
    extern __shared__ __align__(16) char sm[];

    const int tid  = threadIdx.x;
    const int lane = tid & 31;
    const int wid  = tid >> 5;
    const int wm   = wid >> 2;
    const int wn   = wid & 3;
    const int bid  = blockIdx.x;
    const int mt   = bid & 63;
    const int ks   = bid >> 6;
    const int b0   = mt * 64;

    const uint32_t smb = smem_u32(sm);

    float acc[2][4][4];
    #pragma unroll
    for (int mi = 0; mi < 2; mi++)
        #pragma unroll
        for (int nf = 0; nf < 4; nf++)
            #pragma unroll
            for (int i = 0; i < 4; i++) acc[mi][nf][i] = 0.0f;

    // ---- front-batched fp32 X loads: 8 independent LDG.128 (MLP 8) ----
    // thread covers row = tid>>2, 16 floats per pair at float4 cols
    // xb4 + p*16 + (tid&3)*4 + j
    const float* __restrict__ xsrc = (ks < 2) ? sbjs : objs;
    const int xb4  = (ks & 1) * 32;          // float4 base within 64/row
    const int xrow = tid >> 2;
    const int xc4  = (tid & 3) * 4;
    float4 xv[2][4];
    {
        const float4* p = (const float4*)xsrc + (size_t)(b0 + xrow) * 64 + xb4 + xc4;
        #pragma unroll
        for (int j = 0; j < 4; j++) xv[0][j] = p[j];
        #pragma unroll
        for (int j = 0; j < 4; j++) xv[1][j] = p[16 + j];
    }

    // ---- B cp.async: pair groups (lin+sq chunks), 2 commits ----
    {
        #pragma unroll
        for (int p = 0; p < 2; p++) {
            const int klin = ks * 128 + p * 64;
            #pragma unroll
            for (int half = 0; half < 2; half++) {       // 0=lin, 1=sq
                const int kb = klin + half * TWO_D;
                const __nv_bfloat16* gb = g_B + kb;
                uint32_t db = smb + A_ALL + (2 * p + half) * B_CHUNK;
                #pragma unroll
                for (int j = 0; j < 4; j++) {
                    int i = tid + 256 * j;
                    int br = i >> 3, bs = i & 7;
                    CP_ASYNC16(db + br * ROWB + bs * 16,
                               gb + (size_t)br * KDIM + bs * 8);
                }
            }
            CP_COMMIT();
        }
    }

    // ---- convert + STS all 4 A chunks ----
    {
        const uint32_t abase = smb + xrow * ROWB + (tid & 3) * 32;
        #pragma unroll
        for (int p = 0; p < 2; p++) {
            float4 v0 = xv[p][0], v1 = xv[p][1], v2 = xv[p][2], v3 = xv[p][3];
            uint4 lA, lB, sA_, sB_;
            lA.x = bf2pack(v0.x, v0.y);  lA.y = bf2pack(v0.z, v0.w);
            lA.z = bf2pack(v1.x, v1.y);  lA.w = bf2pack(v1.z, v1.w);
            lB.x = bf2pack(v2.x, v2.y);  lB.y = bf2pack(v2.z, v2.w);
            lB.z = bf2pack(v3.x, v3.y);  lB.w = bf2pack(v3.z, v3.w);
            sA_.x = bf2pack(v0.x * v0.x, v0.y * v0.y);
            sA_.y = bf2pack(v0.z * v0.z, v0.w * v0.w);
            sA_.z = bf2pack(v1.x * v1.x, v1.y * v1.y);
            sA_.w = bf2pack(v1.z * v1.z, v1.w * v1.w);
            sB_.x = bf2pack(v2.x * v2.x, v2.y * v2.y);
            sB_.y = bf2pack(v2.z * v2.z, v2.w * v2.w);
            sB_.z = bf2pack(v3.x * v3.x, v3.y * v3.y);
            sB_.w = bf2pack(v3.z * v3.z, v3.w * v3.w);
            uint32_t aLin = abase + (2 * p) * A_CHUNK;
            uint32_t aSq  = abase + (2 * p + 1) * A_CHUNK;
            asm volatile("st.shared.v4.b32 [%0], {%1,%2,%3,%4};" ::
                "r"(aLin), "r"(lA.x), "r"(lA.y), "r"(lA.z), "r"(lA.w));
            asm volatile("st.shared.v4.b32 [%0], {%1,%2,%3,%4};" ::
                "r"(aLin + 16), "r"(lB.x), "r"(lB.y), "r"(lB.z), "r"(lB.w));
            asm volatile("st.shared.v4.b32 [%0], {%1,%2,%3,%4};" ::
                "r"(aSq), "r"(sA_.x), "r"(sA_.y), "r"(sA_.z), "r"(sA_.w));
            asm volatile("st.shared.v4.b32 [%0], {%1,%2,%3,%4};" ::
                "r"(aSq + 16), "r"(sB_.x), "r"(sB_.y), "r"(sB_.z), "r"(sB_.w));
        }
    }

    MmaCtx cx;
    cx.aBase = smb + (wm * 32 + (lane & 15)) * ROWB + (lane >> 4) * 16;
    cx.bBase = smb + A_ALL
             + (wn * 32 + (lane & 7) + ((lane >> 4) << 3)) * ROWB
             + ((lane >> 3) & 1) * 16;
    cx.acc = acc;

    cp_waitg<1>();
    __syncthreads();
    mma_chunk<0>(cx);
    mma_chunk<1>(cx);
    cp_waitg<0>();
    __syncthreads();
    mma_chunk<2>(cx);
    mma_chunk<3>(cx);

    // ---- epilogue: fp32 partials ----
    float* pout = g_partial + (size_t)ks * (BATCH * NREL);
    #pragma unroll
    for (int mi = 0; mi < 2; mi++) {
        const int r0 = b0 + wm * 32 + mi * 16 + (lane >> 2);
        #pragma unroll
        for (int nf = 0; nf < 4; nf++) {
            const float* a = acc[mi][nf];
            int col = wn * 32 + nf * 8 + (lane & 3) * 2;
            *(float2*)&pout[(size_t)r0 * NREL + col] =
                make_float2(a[0], a[1]);
            *(float2*)&pout[(size_t)(r0 + 8) * NREL + col] =
                make_float2(a[2], a[3]);
        }
    }
}

// ---------------------------------------------------------------------------
// out = sum_ks partial[ks] + C  (float4; fixed order = deterministic)
// ---------------------------------------------------------------------------
__global__ void __launch_bounds__(256) nb_reduce(float* __restrict__ out)
{
    const int idx = blockIdx.x * 256 + threadIdx.x;     // float4 index
    const int P   = BATCH * NREL / 4;
    const float4* p = (const float4*)g_partial;
    float4 a = p[idx];
    float4 b = p[idx + P];
    float4 c = p[idx + 2 * P];
    float4 d = p[idx + 3 * P];
    float4 C = ((const float4*)g_C)[idx & (NREL / 4 - 1)];
    float4 o;
    o.x = (a.x + b.x) + (c.x + d.x) + C.x;
    o.y = (a.y + b.y) + (c.y + d.y) + C.y;
    o.z = (a.z + b.z) + (c.z + d.z) + C.z;
    o.w = (a.w + b.w) + (c.w + d.w) + C.w;
    ((float4*)out)[idx] = o;
}

extern "C" void kernel_launch(void* const* d_in, const int* in_sizes, int n_in,
                              void* d_out, int out_size)
{
    const float* sbjs   = (const float*)d_in[0];
    const float* objs   = (const float*)d_in[1];
    const float* mus    = (const float*)d_in[2];
    const float* sigmas = (const float*)d_in[3];
    const float* priors = (const float*)d_in[4];
    float* out = (float*)d_out;

    cudaFuncSetAttribute(nb_mma,
                         cudaFuncAttributeMaxDynamicSharedMemorySize, SMEM_MMA);

    nb_prep<<<NREL, 256>>>(mus, sigmas, priors);
    nb_mma<<<KSPLIT * (BATCH / 64), 256, SMEM_MMA>>>(sbjs, objs);
    nb_reduce<<<(BATCH * NREL / 4) / 256, 256>>>(out);
}